// round 8
// baseline (speedup 1.0000x reference)
#include <cuda_runtime.h>
#include <cuda_fp16.h>
#include <mma.h>

using namespace nvcuda;

// Problem constants
#define B_  2
#define T_  4096
#define H_  8
#define D_  64
#define C_  64
#define C2_ 32                 // tokens per half-chunk (pass1 split)
#define NC_ (T_/C_)            // 64
#define BH_ (B_*H_)            // 16
#define ROWSTRIDE 512          // H_*D_
#define SB_ 72                 // fp16 smem row stride (LDSM conflict-free)
#define SRW_ 68                // fp32 staging stride

#define PLANE_ ((size_t)BH_ * NC_ * D_ * D_)   // halves per partial-S plane

// Scratch: two partial-S fp16 planes (16MB) and fp16 prefix state M (8MB).
__device__ __half g_Sp[2 * PLANE_];
__device__ __half g_M [PLANE_];

typedef wmma::fragment<wmma::matrix_a, 16, 16, 16, __half, wmma::row_major> FragAR;
typedef wmma::fragment<wmma::matrix_a, 16, 16, 16, __half, wmma::col_major> FragAC;
typedef wmma::fragment<wmma::matrix_b, 16, 16, 16, __half, wmma::row_major> FragBR;
typedef wmma::fragment<wmma::matrix_b, 16, 16, 16, __half, wmma::col_major> FragBC;
typedef wmma::fragment<wmma::accumulator, 16, 16, 16, float> FragAcc;

// 2-term split mma on A only: (ahi+alo)*b
#define MMA2(acc, ahi, alo, b)              \
    do {                                    \
        wmma::mma_sync(acc, ahi, b, acc);   \
        wmma::mma_sync(acc, alo, b, acc);   \
    } while (0)

__device__ __forceinline__ void splitA_store4(__half* HI, __half* LO, int idx, float4 x) {
    __half hx = __float2half_rn(x.x);
    __half hy = __float2half_rn(x.y);
    __half hz = __float2half_rn(x.z);
    __half hw = __float2half_rn(x.w);
    __half2 h01 = __halves2half2(hx, hy);
    __half2 h23 = __halves2half2(hz, hw);
    __half2 l01 = __floats2half2_rn(x.x - __half2float(hx), x.y - __half2float(hy));
    __half2 l23 = __floats2half2_rn(x.z - __half2float(hz), x.w - __half2float(hw));
    uint2 hh, ll;
    hh.x = *(unsigned*)&h01; hh.y = *(unsigned*)&h23;
    ll.x = *(unsigned*)&l01; ll.y = *(unsigned*)&l23;
    *(uint2*)&HI[idx] = hh;
    *(uint2*)&LO[idx] = ll;
}

__device__ __forceinline__ void quant_store4(__half* Bq, int idx, float4 x) {
    __half2 h01 = __floats2half2_rn(x.x, x.y);
    __half2 h23 = __floats2half2_rn(x.z, x.w);
    uint2 hh;
    hh.x = *(unsigned*)&h01; hh.y = *(unsigned*)&h23;
    *(uint2*)&Bq[idx] = hh;
}

__device__ __forceinline__ void cp_async16(void* sdst, const void* gsrc) {
    unsigned s = (unsigned)__cvta_generic_to_shared(sdst);
    asm volatile("cp.async.cg.shared.global [%0], [%1], 16;" :: "r"(s), "l"(gsrc));
}
__device__ __forceinline__ void cp_commit() { asm volatile("cp.async.commit_group;"); }
__device__ __forceinline__ void cp_wait0()  { asm volatile("cp.async.wait_group 0;" ::: "memory"); }

// ---------------------------------------------------------------------------
// Pass 1: partial S over 32 tokens per CTA (grid 2048 -> ~13 CTAs/SM).
// S_p[d][e] = sum_{s in half} V[s][d] * K[s][e]; written fp16.
// ---------------------------------------------------------------------------
#define SMEM1_BYTES (D_ * SRW_ * 4)     // 17408 (fp32 staging; fp16 bufs alias: 13824)

__global__ void __launch_bounds__(128) chunk_sum_kernel(const float* __restrict__ k,
                                                        const float* __restrict__ v) {
    extern __shared__ __align__(16) char smraw1[];
    __half* Vhi = (__half*)smraw1;                 // [32][72]
    __half* Vlo = Vhi + C2_ * SB_;
    __half* K16 = Vlo + C2_ * SB_;
    float*  Sraw = (float*)smraw1;                 // [64][68] fp32, aliases after mma

    int blk  = blockIdx.x;            // [0, 2048)
    int half = blk & 1;
    int c    = (blk >> 1) & (NC_ - 1);
    int bh   = blk >> 7;
    int b    = bh >> 3, h = bh & 7;
    int tid  = threadIdx.x;

    size_t tok0 = (size_t)c * C_ + half * C2_;
    const float* kbase = k + (((size_t)b * T_ + tok0) * H_ + h) * D_;
    const float* vbase = v + (((size_t)b * T_ + tok0) * H_ + h) * D_;

    #pragma unroll
    for (int f = tid; f < C2_ * D_ / 4; f += 128) {
        int s = f >> 4;
        int cc = (f & 15) * 4;
        quant_store4(K16, s * SB_ + cc,
                     *(const float4*)(kbase + (size_t)s * ROWSTRIDE + cc));
        splitA_store4(Vhi, Vlo, s * SB_ + cc,
                      *(const float4*)(vbase + (size_t)s * ROWSTRIDE + cc));
    }
    __syncthreads();

    int wid = tid >> 5;
    int d0 = wid * 16;

    FragAcc acc[4];
    #pragma unroll
    for (int j = 0; j < 4; j++) wmma::fill_fragment(acc[j], 0.f);

    #pragma unroll
    for (int kk = 0; kk < 2; kk++) {
        int s0 = kk * 16;
        FragAC ahi, alo;
        wmma::load_matrix_sync(ahi, &Vhi[s0 * SB_ + d0], SB_);   // A(d,s)=V[s][d]
        wmma::load_matrix_sync(alo, &Vlo[s0 * SB_ + d0], SB_);
        #pragma unroll
        for (int j = 0; j < 4; j++) {
            FragBR bq;
            wmma::load_matrix_sync(bq, &K16[s0 * SB_ + j * 16], SB_); // B(s,e)=K[s][e]
            MMA2(acc[j], ahi, alo, bq);
        }
    }
    __syncthreads();   // LDSM reads done before Sraw overwrites

    #pragma unroll
    for (int j = 0; j < 4; j++)
        wmma::store_matrix_sync(&Sraw[d0 * SRW_ + j * 16], acc[j], SRW_, wmma::mem_row_major);
    __syncthreads();

    __half* Sout = g_Sp + (size_t)half * PLANE_ + ((size_t)bh * NC_ + c) * D_ * D_;
    #pragma unroll
    for (int f = tid; f < D_ * D_ / 4; f += 128) {
        int r = f >> 4;
        int cc = (f & 15) * 4;
        quant_store4(Sout, f * 4, *(const float4*)&Sraw[r * SRW_ + cc]);
    }
}

// ---------------------------------------------------------------------------
// Pass 2: sum the two partial planes + exclusive prefix over chunks; fp16 out.
// ---------------------------------------------------------------------------
__global__ void __launch_bounds__(256) prefix_kernel() {
    int gidx = blockIdx.x * 256 + threadIdx.x;   // [0, BH_*2048)
    int bh   = gidx >> 11;
    int pidx = gidx & 2047;
    const __half2* src0 = (const __half2*)g_Sp + (size_t)bh * NC_ * 2048 + pidx;
    const __half2* src1 = src0 + PLANE_ / 2;
    __half2*       dst  = (__half2*)g_M + (size_t)bh * NC_ * 2048 + pidx;

    __half2 v0[NC_];
    #pragma unroll
    for (int c = 0; c < NC_; c++) v0[c] = src0[(size_t)c * 2048];
    float rx = 0.f, ry = 0.f;
    #pragma unroll
    for (int c = 0; c < NC_; c++) {
        float2 a = __half22float2(v0[c]);
        float2 bb = __half22float2(src1[(size_t)c * 2048]);
        dst[(size_t)c * 2048] = __floats2half2_rn(rx, ry);
        rx += a.x + bb.x;
        ry += a.y + bb.y;
    }
}

// ---------------------------------------------------------------------------
// Pass 3: Y = tril(Q K^T) V + Q M_prev^T per (bh, chunk).
// Interleaved QM + QK mma (shared Q fragments); U region reused
// M16 -> fp32 scores -> Shi/Slo (in-place via register staging).
// smem 55.3KB -> 4 CTAs/SM.
// ---------------------------------------------------------------------------
#define HBUF_ (C_ * SB_)                                   // 4608 halves
#define SMEM3_BYTES (4 * HBUF_ * 2 + 2 * HBUF_ * 2)        // 36864 + 18432 = 55296

__global__ void __launch_bounds__(128, 4) output_kernel(const float* __restrict__ q,
                                                        const float* __restrict__ k,
                                                        const float* __restrict__ v,
                                                        float* __restrict__ y) {
    extern __shared__ __align__(16) char smraw[];
    __half* Qhi = (__half*)smraw;
    __half* Qlo = Qhi + HBUF_;
    __half* K16 = Qlo + HBUF_;
    __half* V16 = K16 + HBUF_;
    __half* Ubuf = V16 + HBUF_;       // 9216 halves = 18432B shared region
    __half* M16 = Ubuf;               // [64][72] halves (first 9216B)
    float*  Sraw = (float*)Ubuf;      // [64][72] fp32 (all 18432B)
    __half* Shi = Ubuf;               // [64][72] halves
    __half* Slo = Ubuf + HBUF_;       // [64][72] halves (second 9216B)

    int blk = blockIdx.x;             // [0, 1024)
    int bh  = blk >> 6;
    int c   = blk & (NC_ - 1);
    int b   = bh >> 3, h = bh & 7;
    int tid = threadIdx.x;

    const float* qbase = q + (((size_t)b * T_ + (size_t)c * C_) * H_ + h) * D_;
    const float* kbase = k + (((size_t)b * T_ + (size_t)c * C_) * H_ + h) * D_;
    const float* vbase = v + (((size_t)b * T_ + (size_t)c * C_) * H_ + h) * D_;
    const __half* Mg = g_M + ((size_t)bh * NC_ + c) * D_ * D_;

    // cp.async M16 (fp16, L2-resident) while LDG fills convert Q/K/V
    #pragma unroll
    for (int f = tid; f < D_ * D_ / 8; f += 128) {
        int d = f >> 3;
        int c8 = (f & 7) * 8;
        cp_async16(&M16[d * SB_ + c8], Mg + d * D_ + c8);
    }
    cp_commit();

    #pragma unroll
    for (int f = tid; f < C_ * D_ / 4; f += 128) {
        int s = f >> 4;
        int cc = (f & 15) * 4;
        splitA_store4(Qhi, Qlo, s * SB_ + cc,
                      *(const float4*)(qbase + (size_t)s * ROWSTRIDE + cc));
        quant_store4(K16, s * SB_ + cc,
                     *(const float4*)(kbase + (size_t)s * ROWSTRIDE + cc));
        quant_store4(V16, s * SB_ + cc,
                     *(const float4*)(vbase + (size_t)s * ROWSTRIDE + cc));
    }
    cp_wait0();
    __syncthreads();

    int wid = tid >> 5;
    int t0 = wid * 16;

    FragAcc accY[4], accS[4];
    #pragma unroll
    for (int j = 0; j < 4; j++) {
        wmma::fill_fragment(accY[j], 0.f);
        wmma::fill_fragment(accS[j], 0.f);
    }

    // ---- Interleaved: accY = Q M^T, accS = Q K^T (Q fragments loaded once)
    #pragma unroll
    for (int kk = 0; kk < 4; kk++) {
        int e0 = kk * 16;
        FragAR ahi, alo;
        wmma::load_matrix_sync(ahi, &Qhi[t0 * SB_ + e0], SB_);
        wmma::load_matrix_sync(alo, &Qlo[t0 * SB_ + e0], SB_);
        #pragma unroll
        for (int j = 0; j < 4; j++) {
            FragBC bm;
            wmma::load_matrix_sync(bm, &M16[(j * 16) * SB_ + e0], SB_); // B(e,d)=M[d][e]
            MMA2(accY[j], ahi, alo, bm);
            FragBC bk;
            wmma::load_matrix_sync(bk, &K16[(j * 16) * SB_ + e0], SB_); // B(e,s)=K[s][e]
            MMA2(accS[j], ahi, alo, bk);
        }
    }
    __syncthreads();   // M16 consumed; U region free for fp32 scores

    #pragma unroll
    for (int j = 0; j < 4; j++)
        wmma::store_matrix_sync(&Sraw[t0 * SB_ + j * 16], accS[j], SB_, wmma::mem_row_major);
    __syncthreads();

    // ---- Causal mask + fp16 split, in place (register staging)
    float r[32];
    #pragma unroll
    for (int i = 0; i < 32; i++) {
        int f = tid + i * 128;
        int t = f >> 6, s = f & 63;
        r[i] = Sraw[t * SB_ + s];
    }
    __syncthreads();   // all fp32 reads done before fp16 overwrite
    #pragma unroll
    for (int i = 0; i < 32; i++) {
        int f = tid + i * 128;
        int t = f >> 6, s = f & 63;
        float x = (s <= t) ? r[i] : 0.f;
        __half hi = __float2half_rn(x);
        Shi[t * SB_ + s] = hi;
        Slo[t * SB_ + s] = __float2half_rn(x - __half2float(hi));
    }
    __syncthreads();

    // ---- accY += A V
    #pragma unroll
    for (int kk = 0; kk < 4; kk++) {
        int s0 = kk * 16;
        FragAR ahi, alo;
        wmma::load_matrix_sync(ahi, &Shi[t0 * SB_ + s0], SB_);
        wmma::load_matrix_sync(alo, &Slo[t0 * SB_ + s0], SB_);
        #pragma unroll
        for (int j = 0; j < 4; j++) {
            FragBR bv;
            wmma::load_matrix_sync(bv, &V16[s0 * SB_ + j * 16], SB_);  // B(s,d)=V[s][d]
            MMA2(accY[j], ahi, alo, bv);
        }
    }

    float* ybase = y + (((size_t)b * T_ + (size_t)c * C_) * H_ + h) * D_;
    #pragma unroll
    for (int j = 0; j < 4; j++)
        wmma::store_matrix_sync(ybase + (size_t)t0 * ROWSTRIDE + j * 16, accY[j],
                                ROWSTRIDE, wmma::mem_row_major);
}

// ---------------------------------------------------------------------------
extern "C" void kernel_launch(void* const* d_in, const int* in_sizes, int n_in,
                              void* d_out, int out_size) {
    (void)in_sizes; (void)n_in; (void)out_size;
    const float* q = (const float*)d_in[0];
    const float* k = (const float*)d_in[1];
    const float* v = (const float*)d_in[2];
    float* y = (float*)d_out;

    cudaFuncSetAttribute(output_kernel, cudaFuncAttributeMaxDynamicSharedMemorySize,
                         SMEM3_BYTES);

    chunk_sum_kernel<<<BH_ * NC_ * 2, 128, SMEM1_BYTES>>>(k, v);
    prefix_kernel<<<(BH_ * 2048) / 256, 256>>>();
    output_kernel<<<BH_ * NC_, 128, SMEM3_BYTES>>>(q, k, v, y);
}

// round 10
// speedup vs baseline: 1.3077x; 1.3077x over previous
#include <cuda_runtime.h>
#include <cuda_fp16.h>
#include <mma.h>

using namespace nvcuda;

// Problem constants
#define B_  2
#define T_  4096
#define H_  8
#define D_  64
#define C_  64
#define NC_ (T_/C_)            // 64
#define BH_ (B_*H_)            // 16
#define ROWSTRIDE 512          // H_*D_
#define SB_ 72                 // fp16 smem row stride (LDSM conflict-free)
#define HB_ (C_ * SB_)         // 4608 halves = 9216 bytes per buffer

// Scratch: fp32 chunk sums (16MB) and fp16 exclusive-prefix state (8MB).
__device__ float  g_Sf[(size_t)BH_ * NC_ * D_ * D_];
__device__ __half g_M [(size_t)BH_ * NC_ * D_ * D_];

typedef wmma::fragment<wmma::matrix_a, 16, 16, 16, __half, wmma::row_major> FragAR;
typedef wmma::fragment<wmma::matrix_a, 16, 16, 16, __half, wmma::col_major> FragAC;
typedef wmma::fragment<wmma::matrix_b, 16, 16, 16, __half, wmma::row_major> FragBR;
typedef wmma::fragment<wmma::matrix_b, 16, 16, 16, __half, wmma::col_major> FragBC;
typedef wmma::fragment<wmma::accumulator, 16, 16, 16, float> FragAcc;

// 2-term split mma on A only: (ahi+alo)*b
#define MMA2(acc, ahi, alo, b)              \
    do {                                    \
        wmma::mma_sync(acc, ahi, b, acc);   \
        wmma::mma_sync(acc, alo, b, acc);   \
    } while (0)

__device__ __forceinline__ void splitA_store4(__half* HI, __half* LO, int idx, float4 x) {
    __half hx = __float2half_rn(x.x);
    __half hy = __float2half_rn(x.y);
    __half hz = __float2half_rn(x.z);
    __half hw = __float2half_rn(x.w);
    __half2 h01 = __halves2half2(hx, hy);
    __half2 h23 = __halves2half2(hz, hw);
    __half2 l01 = __floats2half2_rn(x.x - __half2float(hx), x.y - __half2float(hy));
    __half2 l23 = __floats2half2_rn(x.z - __half2float(hz), x.w - __half2float(hw));
    uint2 hh, ll;
    hh.x = *(unsigned*)&h01; hh.y = *(unsigned*)&h23;
    ll.x = *(unsigned*)&l01; ll.y = *(unsigned*)&l23;
    *(uint2*)&HI[idx] = hh;
    *(uint2*)&LO[idx] = ll;
}

__device__ __forceinline__ void quant_store4(__half* Bq, int idx, float4 x) {
    __half2 h01 = __floats2half2_rn(x.x, x.y);
    __half2 h23 = __floats2half2_rn(x.z, x.w);
    uint2 hh;
    hh.x = *(unsigned*)&h01; hh.y = *(unsigned*)&h23;
    *(uint2*)&Bq[idx] = hh;
}

__device__ __forceinline__ void cp_async16(void* sdst, const void* gsrc) {
    unsigned s = (unsigned)__cvta_generic_to_shared(sdst);
    asm volatile("cp.async.cg.shared.global [%0], [%1], 16;" :: "r"(s), "l"(gsrc));
}
__device__ __forceinline__ void cp_commit() { asm volatile("cp.async.commit_group;"); }
__device__ __forceinline__ void cp_wait0()  { asm volatile("cp.async.wait_group 0;" ::: "memory"); }

// ---------------------------------------------------------------------------
// Pass 1: S[d][e] = sum_s V[s][d] * K[s][e] per (bh, chunk).
// Accumulators stored DIRECTLY to the fp32 global plane (no smem roundtrip).
// ---------------------------------------------------------------------------
#define SMEM1_BYTES (3 * HB_ * 2)   // 27648

__global__ void __launch_bounds__(128) chunk_sum_kernel(const float* __restrict__ k,
                                                        const float* __restrict__ v) {
    extern __shared__ __align__(16) char smraw1[];
    __half* Vhi = (__half*)smraw1;
    __half* Vlo = Vhi + HB_;
    __half* K16 = Vlo + HB_;

    int blk = blockIdx.x;             // [0, 1024)
    int bh  = blk >> 6;
    int c   = blk & (NC_ - 1);
    int b   = bh >> 3, h = bh & 7;
    int tid = threadIdx.x;

    const float* kbase = k + (((size_t)b * T_ + (size_t)c * C_) * H_ + h) * D_;
    const float* vbase = v + (((size_t)b * T_ + (size_t)c * C_) * H_ + h) * D_;

    #pragma unroll
    for (int f = tid; f < C_ * D_ / 4; f += 128) {
        int s = f >> 4;
        int cc = (f & 15) * 4;
        quant_store4(K16, s * SB_ + cc,
                     *(const float4*)(kbase + (size_t)s * ROWSTRIDE + cc));
        splitA_store4(Vhi, Vlo, s * SB_ + cc,
                      *(const float4*)(vbase + (size_t)s * ROWSTRIDE + cc));
    }
    __syncthreads();

    int wid = tid >> 5;
    int d0 = wid * 16;

    FragAcc acc[4];
    #pragma unroll
    for (int j = 0; j < 4; j++) wmma::fill_fragment(acc[j], 0.f);

    #pragma unroll
    for (int kk = 0; kk < 4; kk++) {
        int s0 = kk * 16;
        FragAC ahi, alo;
        wmma::load_matrix_sync(ahi, &Vhi[s0 * SB_ + d0], SB_);   // A(d,s)=V[s][d]
        wmma::load_matrix_sync(alo, &Vlo[s0 * SB_ + d0], SB_);
        #pragma unroll
        for (int j = 0; j < 4; j++) {
            FragBR bq;
            wmma::load_matrix_sync(bq, &K16[s0 * SB_ + j * 16], SB_); // B(s,e)=K[s][e]
            MMA2(acc[j], ahi, alo, bq);
        }
    }

    // Direct fp32 store to global scratch (L2-resident)
    float* Sout = g_Sf + (size_t)blk * D_ * D_;
    #pragma unroll
    for (int j = 0; j < 4; j++)
        wmma::store_matrix_sync(&Sout[d0 * D_ + j * 16], acc[j], D_, wmma::mem_row_major);
}

// ---------------------------------------------------------------------------
// Pass 2: exclusive prefix over the chunk axis; fp32 in (S), fp16 out (M).
// One float column per thread; 64 loads batched for MLP.
// ---------------------------------------------------------------------------
__global__ void __launch_bounds__(256) prefix_kernel() {
    int gidx = blockIdx.x * 256 + threadIdx.x;   // [0, BH_*4096)
    int bh   = gidx >> 12;
    int idx  = gidx & 4095;
    const float* src = g_Sf + (size_t)bh * NC_ * 4096 + idx;
    __half*      dst = g_M  + (size_t)bh * NC_ * 4096 + idx;

    float vals[NC_];
    #pragma unroll
    for (int c = 0; c < NC_; c++) vals[c] = src[(size_t)c * 4096];
    float run = 0.f;
    #pragma unroll
    for (int c = 0; c < NC_; c++) {
        dst[(size_t)c * 4096] = __float2half_rn(run);
        run += vals[c];
    }
}

// ---------------------------------------------------------------------------
// Pass 3: Y = tril(Q K^T) V + Q M_prev^T per (bh, chunk).
// Sequential phases, single live acc set. fp32 scores and fp16 Shi/Slo share
// one 18KB region (register-staged in-place mask, proven in R8). M cp.async'd
// into the dead K16 buffer. smem 55.3KB -> 4 CTAs/SM.
// ---------------------------------------------------------------------------
#define SMEM3_BYTES (4 * HB_ * 2 + HB_ * 4)   // 36864 + 18432 = 55296

__global__ void __launch_bounds__(128, 4) output_kernel(const float* __restrict__ q,
                                                        const float* __restrict__ k,
                                                        const float* __restrict__ v,
                                                        float* __restrict__ y) {
    extern __shared__ __align__(16) char smraw[];
    __half* Qhi = (__half*)smraw;
    __half* Qlo = Qhi + HB_;
    __half* K16 = Qlo + HB_;
    __half* V16 = K16 + HB_;
    float*  Sraw = (float*)(V16 + HB_);   // fp32 [64][72] (18432B region)
    __half* Shi  = (__half*)Sraw;         // halves [64][72] (first 9216B)
    __half* Slo  = Shi + HB_;             // halves [64][72] (second 9216B)
    __half* M16  = K16;                   // reused after QK phase

    int blk = blockIdx.x;             // [0, 1024)
    int bh  = blk >> 6;
    int c   = blk & (NC_ - 1);
    int b   = bh >> 3, h = bh & 7;
    int tid = threadIdx.x;

    const float* qbase = q + (((size_t)b * T_ + (size_t)c * C_) * H_ + h) * D_;
    const float* kbase = k + (((size_t)b * T_ + (size_t)c * C_) * H_ + h) * D_;
    const float* vbase = v + (((size_t)b * T_ + (size_t)c * C_) * H_ + h) * D_;
    const __half* Mg = g_M + (size_t)blk * D_ * D_;

    #pragma unroll
    for (int f = tid; f < C_ * D_ / 4; f += 128) {
        int s = f >> 4;
        int cc = (f & 15) * 4;
        splitA_store4(Qhi, Qlo, s * SB_ + cc,
                      *(const float4*)(qbase + (size_t)s * ROWSTRIDE + cc));
        quant_store4(K16, s * SB_ + cc,
                     *(const float4*)(kbase + (size_t)s * ROWSTRIDE + cc));
        quant_store4(V16, s * SB_ + cc,
                     *(const float4*)(vbase + (size_t)s * ROWSTRIDE + cc));
    }
    __syncthreads();

    int wid = tid >> 5;
    int t0 = wid * 16;

    // ---- Phase 1: scores S[t][s] = sum_e Q[t][e] K[s][e]
    FragAcc acc[4];
    #pragma unroll
    for (int j = 0; j < 4; j++) wmma::fill_fragment(acc[j], 0.f);
    #pragma unroll
    for (int kk = 0; kk < 4; kk++) {
        int e0 = kk * 16;
        FragAR ahi, alo;
        wmma::load_matrix_sync(ahi, &Qhi[t0 * SB_ + e0], SB_);
        wmma::load_matrix_sync(alo, &Qlo[t0 * SB_ + e0], SB_);
        #pragma unroll
        for (int j = 0; j < 4; j++) {
            FragBC bk;
            wmma::load_matrix_sync(bk, &K16[(j * 16) * SB_ + e0], SB_); // B(e,s)=K[s][e]
            MMA2(acc[j], ahi, alo, bk);
        }
    }
    #pragma unroll
    for (int j = 0; j < 4; j++)
        wmma::store_matrix_sync(&Sraw[t0 * SB_ + j * 16], acc[j], SB_, wmma::mem_row_major);
    __syncthreads();   // all K16 reads + Sraw stores complete

    // ---- cp.async M into the dead K16 buffer (overlaps the mask below)
    #pragma unroll
    for (int f = tid; f < D_ * D_ / 8; f += 128) {
        int d = f >> 3;
        int c8 = (f & 7) * 8;
        cp_async16(&M16[d * SB_ + c8], Mg + d * D_ + c8);
    }
    cp_commit();

    // ---- Causal mask (s <= t) + fp16 split, in place via register staging
    float r[32];
    #pragma unroll
    for (int i = 0; i < 32; i++) {
        int f = tid + i * 128;
        int t = f >> 6, s = f & 63;
        r[i] = Sraw[t * SB_ + s];
    }
    __syncthreads();   // all fp32 reads done before fp16 overwrite
    #pragma unroll
    for (int i = 0; i < 32; i++) {
        int f = tid + i * 128;
        int t = f >> 6, s = f & 63;
        float x = (s <= t) ? r[i] : 0.f;
        __half hi = __float2half_rn(x);
        Shi[t * SB_ + s] = hi;
        Slo[t * SB_ + s] = __float2half_rn(x - __half2float(hi));
    }
    cp_wait0();
    __syncthreads();

    // ---- Phase 2: Y = Q M^T + A V (fresh single acc set)
    #pragma unroll
    for (int j = 0; j < 4; j++) wmma::fill_fragment(acc[j], 0.f);
    #pragma unroll
    for (int kk = 0; kk < 4; kk++) {
        int e0 = kk * 16;
        FragAR ahi, alo;
        wmma::load_matrix_sync(ahi, &Qhi[t0 * SB_ + e0], SB_);
        wmma::load_matrix_sync(alo, &Qlo[t0 * SB_ + e0], SB_);
        #pragma unroll
        for (int j = 0; j < 4; j++) {
            FragBC bm;
            wmma::load_matrix_sync(bm, &M16[(j * 16) * SB_ + e0], SB_); // B(e,d)=M[d][e]
            MMA2(acc[j], ahi, alo, bm);
        }
    }
    #pragma unroll
    for (int kk = 0; kk < 4; kk++) {
        int s0 = kk * 16;
        FragAR ahi, alo;
        wmma::load_matrix_sync(ahi, &Shi[t0 * SB_ + s0], SB_);
        wmma::load_matrix_sync(alo, &Slo[t0 * SB_ + s0], SB_);
        #pragma unroll
        for (int j = 0; j < 4; j++) {
            FragBR bv;
            wmma::load_matrix_sync(bv, &V16[s0 * SB_ + j * 16], SB_);  // B(s,d)=V[s][d]
            MMA2(acc[j], ahi, alo, bv);
        }
    }

    float* ybase = y + (((size_t)b * T_ + (size_t)c * C_) * H_ + h) * D_;
    #pragma unroll
    for (int j = 0; j < 4; j++)
        wmma::store_matrix_sync(ybase + (size_t)t0 * ROWSTRIDE + j * 16, acc[j],
                                ROWSTRIDE, wmma::mem_row_major);
}

// ---------------------------------------------------------------------------
extern "C" void kernel_launch(void* const* d_in, const int* in_sizes, int n_in,
                              void* d_out, int out_size) {
    (void)in_sizes; (void)n_in; (void)out_size;
    const float* q = (const float*)d_in[0];
    const float* k = (const float*)d_in[1];
    const float* v = (const float*)d_in[2];
    float* y = (float*)d_out;

    cudaFuncSetAttribute(output_kernel, cudaFuncAttributeMaxDynamicSharedMemorySize,
                         SMEM3_BYTES);

    chunk_sum_kernel<<<BH_ * NC_, 128, SMEM1_BYTES>>>(k, v);
    prefix_kernel<<<(BH_ * 4096) / 256, 256>>>();
    output_kernel<<<BH_ * NC_, 128, SMEM3_BYTES>>>(q, k, v, y);
}

// round 11
// speedup vs baseline: 1.3090x; 1.0010x over previous
#include <cuda_runtime.h>
#include <cuda_fp16.h>
#include <mma.h>

using namespace nvcuda;

// Problem constants
#define B_  2
#define T_  4096
#define H_  8
#define D_  64
#define C_  64
#define NC_ (T_/C_)            // 64
#define BH_ (B_*H_)            // 16
#define ROWSTRIDE 512          // H_*D_
#define SB_ 72                 // fp16 smem row stride (LDSM conflict-free)
#define HB_ (C_ * SB_)         // 4608 halves = 9216 bytes per buffer
#define SRW_ 68                // fp32 pack-staging stride

// Scratch: fp16 chunk sums and fp16 exclusive-prefix state. 8MB each, L2-resident.
__device__ __half g_Sh[(size_t)BH_ * NC_ * D_ * D_];
__device__ __half g_M [(size_t)BH_ * NC_ * D_ * D_];

typedef wmma::fragment<wmma::matrix_a, 16, 16, 16, __half, wmma::row_major> FragAR;
typedef wmma::fragment<wmma::matrix_a, 16, 16, 16, __half, wmma::col_major> FragAC;
typedef wmma::fragment<wmma::matrix_b, 16, 16, 16, __half, wmma::row_major> FragBR;
typedef wmma::fragment<wmma::matrix_b, 16, 16, 16, __half, wmma::col_major> FragBC;
typedef wmma::fragment<wmma::accumulator, 16, 16, 16, float> FragAcc;

// 2-term split mma on A only: (ahi+alo)*b
#define MMA2(acc, ahi, alo, b)              \
    do {                                    \
        wmma::mma_sync(acc, ahi, b, acc);   \
        wmma::mma_sync(acc, alo, b, acc);   \
    } while (0)

__device__ __forceinline__ void splitA_store4(__half* HI, __half* LO, int idx, float4 x) {
    __half hx = __float2half_rn(x.x);
    __half hy = __float2half_rn(x.y);
    __half hz = __float2half_rn(x.z);
    __half hw = __float2half_rn(x.w);
    __half2 h01 = __halves2half2(hx, hy);
    __half2 h23 = __halves2half2(hz, hw);
    __half2 l01 = __floats2half2_rn(x.x - __half2float(hx), x.y - __half2float(hy));
    __half2 l23 = __floats2half2_rn(x.z - __half2float(hz), x.w - __half2float(hw));
    uint2 hh, ll;
    hh.x = *(unsigned*)&h01; hh.y = *(unsigned*)&h23;
    ll.x = *(unsigned*)&l01; ll.y = *(unsigned*)&l23;
    *(uint2*)&HI[idx] = hh;
    *(uint2*)&LO[idx] = ll;
}

__device__ __forceinline__ void quant_store4(__half* Bq, int idx, float4 x) {
    __half2 h01 = __floats2half2_rn(x.x, x.y);
    __half2 h23 = __floats2half2_rn(x.z, x.w);
    uint2 hh;
    hh.x = *(unsigned*)&h01; hh.y = *(unsigned*)&h23;
    *(uint2*)&Bq[idx] = hh;
}

__device__ __forceinline__ void cp_async16(void* sdst, const void* gsrc) {
    unsigned s = (unsigned)__cvta_generic_to_shared(sdst);
    asm volatile("cp.async.cg.shared.global [%0], [%1], 16;" :: "r"(s), "l"(gsrc));
}
__device__ __forceinline__ void cp_commit() { asm volatile("cp.async.commit_group;"); }
__device__ __forceinline__ void cp_wait0()  { asm volatile("cp.async.wait_group 0;" ::: "memory"); }

// ---------------------------------------------------------------------------
// Pass 1: S[d][e] = sum_s V[s][d] * K[s][e] per (bh, chunk); S written fp16.
// K,V streamed via cp.async into an fp32 stage (high MLP, no reg pressure),
// then converted from smem. Sraw pack-staging aliases the dead stage.
// ---------------------------------------------------------------------------
#define SMEM1_STAGE (2 * C_ * D_ * 4)                 // 32768
#define SMEM1_BYTES (SMEM1_STAGE + 3 * HB_ * 2)       // 60416

__global__ void __launch_bounds__(128) chunk_sum_kernel(const float* __restrict__ k,
                                                        const float* __restrict__ v) {
    extern __shared__ __align__(16) char smraw1[];
    float* Kst = (float*)smraw1;                      // [64][64] fp32 stage
    float* Vst = Kst + C_ * D_;
    float* Sraw = (float*)smraw1;                     // [64][68] fp32, aliases stage
    __half* K16 = (__half*)(smraw1 + SMEM1_STAGE);
    __half* Vhi = K16 + HB_;
    __half* Vlo = Vhi + HB_;

    int blk = blockIdx.x;             // [0, 1024)
    int bh  = blk >> 6;
    int c   = blk & (NC_ - 1);
    int b   = bh >> 3, h = bh & 7;
    int tid = threadIdx.x;

    const float* kbase = k + (((size_t)b * T_ + (size_t)c * C_) * H_ + h) * D_;
    const float* vbase = v + (((size_t)b * T_ + (size_t)c * C_) * H_ + h) * D_;

    // Fire all loads (32 cp.async per thread, fire-and-forget)
    #pragma unroll
    for (int f = tid; f < C_ * D_ / 4; f += 128) {
        int s = f >> 4, c4 = f & 15;
        cp_async16(&Kst[f * 4], kbase + (size_t)s * ROWSTRIDE + c4 * 4);
        cp_async16(&Vst[f * 4], vbase + (size_t)s * ROWSTRIDE + c4 * 4);
    }
    cp_commit();
    cp_wait0();
    __syncthreads();

    // Convert from smem stage
    #pragma unroll
    for (int f = tid; f < C_ * D_ / 4; f += 128) {
        int s = f >> 4;
        int cc = (f & 15) * 4;
        quant_store4(K16, s * SB_ + cc, *(float4*)&Kst[f * 4]);
        splitA_store4(Vhi, Vlo, s * SB_ + cc, *(float4*)&Vst[f * 4]);
    }
    __syncthreads();   // stage now dead

    int wid = tid >> 5;
    int d0 = wid * 16;

    FragAcc acc[4];
    #pragma unroll
    for (int j = 0; j < 4; j++) wmma::fill_fragment(acc[j], 0.f);

    #pragma unroll
    for (int kk = 0; kk < 4; kk++) {
        int s0 = kk * 16;
        FragAC ahi, alo;
        wmma::load_matrix_sync(ahi, &Vhi[s0 * SB_ + d0], SB_);   // A(d,s)=V[s][d]
        wmma::load_matrix_sync(alo, &Vlo[s0 * SB_ + d0], SB_);
        #pragma unroll
        for (int j = 0; j < 4; j++) {
            FragBR bq;
            wmma::load_matrix_sync(bq, &K16[s0 * SB_ + j * 16], SB_); // B(s,e)=K[s][e]
            MMA2(acc[j], ahi, alo, bq);
        }
    }

    // Pack S via the dead stage region (fp32) -> fp16 gmem
    #pragma unroll
    for (int j = 0; j < 4; j++)
        wmma::store_matrix_sync(&Sraw[d0 * SRW_ + j * 16], acc[j], SRW_, wmma::mem_row_major);
    __syncthreads();

    __half* Sout = g_Sh + (size_t)blk * D_ * D_;
    #pragma unroll
    for (int f = tid; f < D_ * D_ / 4; f += 128) {
        int r = f >> 4;
        int cc = (f & 15) * 4;
        quant_store4(Sout, f * 4, *(const float4*)&Sraw[r * SRW_ + cc]);
    }
}

// ---------------------------------------------------------------------------
// Pass 2: exclusive prefix over the chunk axis; fp16 in (S), fp16 out (M).
// ---------------------------------------------------------------------------
__global__ void __launch_bounds__(256) prefix_kernel() {
    int gidx = blockIdx.x * 256 + threadIdx.x;   // [0, BH_*2048)
    int bh   = gidx >> 11;
    int pidx = gidx & 2047;
    const __half2* src = (const __half2*)g_Sh + (size_t)bh * NC_ * 2048 + pidx;
    __half2*       dst = (__half2*)g_M  + (size_t)bh * NC_ * 2048 + pidx;

    __half2 vals[NC_];
    #pragma unroll
    for (int c = 0; c < NC_; c++) vals[c] = src[(size_t)c * 2048];
    float rx = 0.f, ry = 0.f;
    #pragma unroll
    for (int c = 0; c < NC_; c++) {
        float2 t = __half22float2(vals[c]);
        dst[(size_t)c * 2048] = __floats2half2_rn(rx, ry);
        rx += t.x; ry += t.y;
    }
}

// ---------------------------------------------------------------------------
// Pass 3: Y = tril(Q K^T) V + Q M_prev^T per (bh, chunk).
// K,V via cp.async stage (reused for Sraw/Shi/Slo and M16 after convert);
// Q via LDG+split overlapping the cp.async wait. smem 68KB -> 3 CTAs/SM.
// ---------------------------------------------------------------------------
#define SMEM3_STAGE (2 * C_ * D_ * 4)                 // 32768
#define SMEM3_BYTES (SMEM3_STAGE + 4 * HB_ * 2)       // 69632

__global__ void __launch_bounds__(128) output_kernel(const float* __restrict__ q,
                                                     const float* __restrict__ k,
                                                     const float* __restrict__ v,
                                                     float* __restrict__ y) {
    extern __shared__ __align__(16) char smraw[];
    float* Kst = (float*)smraw;                       // [64][64] fp32 stage
    float* Vst = Kst + C_ * D_;
    // Stage region reused after convert:
    float*  Sraw = (float*)smraw;                     // [64][72] fp32 = 18432B
    __half* Shi  = (__half*)smraw;                    // first 9216B
    __half* Slo  = Shi + HB_;                         // second 9216B
    __half* M16  = (__half*)(smraw + 18432);          // 9216B (disjoint from Sraw)
    // Persistent fp16 buffers:
    __half* Qhi = (__half*)(smraw + SMEM3_STAGE);
    __half* Qlo = Qhi + HB_;
    __half* K16 = Qlo + HB_;
    __half* V16 = K16 + HB_;

    int blk = blockIdx.x;             // [0, 1024)
    int bh  = blk >> 6;
    int c   = blk & (NC_ - 1);
    int b   = bh >> 3, h = bh & 7;
    int tid = threadIdx.x;

    const float* qbase = q + (((size_t)b * T_ + (size_t)c * C_) * H_ + h) * D_;
    const float* kbase = k + (((size_t)b * T_ + (size_t)c * C_) * H_ + h) * D_;
    const float* vbase = v + (((size_t)b * T_ + (size_t)c * C_) * H_ + h) * D_;
    const __half* Mg = g_M + (size_t)blk * D_ * D_;

    // Fire K,V cp.async first...
    #pragma unroll
    for (int f = tid; f < C_ * D_ / 4; f += 128) {
        int s = f >> 4, c4 = f & 15;
        cp_async16(&Kst[f * 4], kbase + (size_t)s * ROWSTRIDE + c4 * 4);
        cp_async16(&Vst[f * 4], vbase + (size_t)s * ROWSTRIDE + c4 * 4);
    }
    cp_commit();

    // ...then load+split Q via LDG (overlaps the cp.async stream)
    #pragma unroll
    for (int f = tid; f < C_ * D_ / 4; f += 128) {
        int s = f >> 4;
        int cc = (f & 15) * 4;
        splitA_store4(Qhi, Qlo, s * SB_ + cc,
                      *(const float4*)(qbase + (size_t)s * ROWSTRIDE + cc));
    }
    cp_wait0();
    __syncthreads();

    // Convert K,V from the stage
    #pragma unroll
    for (int f = tid; f < C_ * D_ / 4; f += 128) {
        int s = f >> 4;
        int cc = (f & 15) * 4;
        quant_store4(K16, s * SB_ + cc, *(float4*)&Kst[f * 4]);
        quant_store4(V16, s * SB_ + cc, *(float4*)&Vst[f * 4]);
    }
    __syncthreads();   // stage dead

    // Prefetch M into the stage region (overlaps the QK mma below)
    #pragma unroll
    for (int f = tid; f < D_ * D_ / 8; f += 128) {
        int d = f >> 3;
        int c8 = (f & 7) * 8;
        cp_async16(&M16[d * SB_ + c8], Mg + d * D_ + c8);
    }
    cp_commit();

    int wid = tid >> 5;
    int t0 = wid * 16;

    // ---- Phase 1: scores S[t][s] = sum_e Q[t][e] K[s][e]
    FragAcc acc[4];
    #pragma unroll
    for (int j = 0; j < 4; j++) wmma::fill_fragment(acc[j], 0.f);
    #pragma unroll
    for (int kk = 0; kk < 4; kk++) {
        int e0 = kk * 16;
        FragAR ahi, alo;
        wmma::load_matrix_sync(ahi, &Qhi[t0 * SB_ + e0], SB_);
        wmma::load_matrix_sync(alo, &Qlo[t0 * SB_ + e0], SB_);
        #pragma unroll
        for (int j = 0; j < 4; j++) {
            FragBC bk;
            wmma::load_matrix_sync(bk, &K16[(j * 16) * SB_ + e0], SB_); // B(e,s)=K[s][e]
            MMA2(acc[j], ahi, alo, bk);
        }
    }
    #pragma unroll
    for (int j = 0; j < 4; j++)
        wmma::store_matrix_sync(&Sraw[t0 * SB_ + j * 16], acc[j], SB_, wmma::mem_row_major);
    __syncthreads();

    // ---- Causal mask (s <= t) + fp16 split, in place via register staging
    float r[32];
    #pragma unroll
    for (int i = 0; i < 32; i++) {
        int f = tid + i * 128;
        int t = f >> 6, s = f & 63;
        r[i] = Sraw[t * SB_ + s];
    }
    __syncthreads();   // all fp32 reads done before fp16 overwrite
    #pragma unroll
    for (int i = 0; i < 32; i++) {
        int f = tid + i * 128;
        int t = f >> 6, s = f & 63;
        float x = (s <= t) ? r[i] : 0.f;
        __half hi = __float2half_rn(x);
        Shi[t * SB_ + s] = hi;
        Slo[t * SB_ + s] = __float2half_rn(x - __half2float(hi));
    }
    cp_wait0();        // M16 ready
    __syncthreads();

    // ---- Phase 2: Y = Q M^T + A V (fresh single acc set)
    #pragma unroll
    for (int j = 0; j < 4; j++) wmma::fill_fragment(acc[j], 0.f);
    #pragma unroll
    for (int kk = 0; kk < 4; kk++) {
        int e0 = kk * 16;
        FragAR ahi, alo;
        wmma::load_matrix_sync(ahi, &Qhi[t0 * SB_ + e0], SB_);
        wmma::load_matrix_sync(alo, &Qlo[t0 * SB_ + e0], SB_);
        #pragma unroll
        for (int j = 0; j < 4; j++) {
            FragBC bm;
            wmma::load_matrix_sync(bm, &M16[(j * 16) * SB_ + e0], SB_); // B(e,d)=M[d][e]
            MMA2(acc[j], ahi, alo, bm);
        }
    }
    #pragma unroll
    for (int kk = 0; kk < 4; kk++) {
        int s0 = kk * 16;
        FragAR ahi, alo;
        wmma::load_matrix_sync(ahi, &Shi[t0 * SB_ + s0], SB_);
        wmma::load_matrix_sync(alo, &Slo[t0 * SB_ + s0], SB_);
        #pragma unroll
        for (int j = 0; j < 4; j++) {
            FragBR bv;
            wmma::load_matrix_sync(bv, &V16[s0 * SB_ + j * 16], SB_);  // B(s,d)=V[s][d]
            MMA2(acc[j], ahi, alo, bv);
        }
    }

    float* ybase = y + (((size_t)b * T_ + (size_t)c * C_) * H_ + h) * D_;
    #pragma unroll
    for (int j = 0; j < 4; j++)
        wmma::store_matrix_sync(ybase + (size_t)t0 * ROWSTRIDE + j * 16, acc[j],
                                ROWSTRIDE, wmma::mem_row_major);
}

// ---------------------------------------------------------------------------
extern "C" void kernel_launch(void* const* d_in, const int* in_sizes, int n_in,
                              void* d_out, int out_size) {
    (void)in_sizes; (void)n_in; (void)out_size;
    const float* q = (const float*)d_in[0];
    const float* k = (const float*)d_in[1];
    const float* v = (const float*)d_in[2];
    float* y = (float*)d_out;

    cudaFuncSetAttribute(chunk_sum_kernel, cudaFuncAttributeMaxDynamicSharedMemorySize,
                         SMEM1_BYTES);
    cudaFuncSetAttribute(output_kernel, cudaFuncAttributeMaxDynamicSharedMemorySize,
                         SMEM3_BYTES);

    chunk_sum_kernel<<<BH_ * NC_, 128, SMEM1_BYTES>>>(k, v);
    prefix_kernel<<<(BH_ * 2048) / 256, 256>>>();
    output_kernel<<<BH_ * NC_, 128, SMEM3_BYTES>>>(q, k, v, y);
}

// round 12
// speedup vs baseline: 1.6038x; 1.2252x over previous
#include <cuda_runtime.h>
#include <cuda_fp16.h>
#include <mma.h>

using namespace nvcuda;

// Problem constants
#define B_  2
#define T_  4096
#define H_  8
#define D_  64
#define C_  64
#define NC_ (T_/C_)            // 64
#define BH_ (B_*H_)            // 16
#define ROWSTRIDE 512          // H_*D_
#define SB_ 72                 // fp16 smem row stride (LDSM conflict-free)
#define HB_ (C_ * SB_)         // 4608 halves = 9216 bytes per buffer
#define SRW_ 68                // fp32 pack-staging stride

// Scratch: fp16 chunk sums and fp16 exclusive-prefix state. 8MB each, L2-resident.
__device__ __half g_Sh[(size_t)BH_ * NC_ * D_ * D_];
__device__ __half g_M [(size_t)BH_ * NC_ * D_ * D_];

typedef wmma::fragment<wmma::matrix_a, 16, 16, 16, __half, wmma::row_major> FragAR;
typedef wmma::fragment<wmma::matrix_a, 16, 16, 16, __half, wmma::col_major> FragAC;
typedef wmma::fragment<wmma::matrix_b, 16, 16, 16, __half, wmma::row_major> FragBR;
typedef wmma::fragment<wmma::matrix_b, 16, 16, 16, __half, wmma::col_major> FragBC;
typedef wmma::fragment<wmma::accumulator, 16, 16, 16, float> FragAcc;

// Quantize 4 fp32 to fp16 and store (8B store).
__device__ __forceinline__ void quant_store4(__half* Bq, int idx, float4 x) {
    __half2 h01 = __floats2half2_rn(x.x, x.y);
    __half2 h23 = __floats2half2_rn(x.z, x.w);
    uint2 hh;
    hh.x = *(unsigned*)&h01; hh.y = *(unsigned*)&h23;
    *(uint2*)&Bq[idx] = hh;
}

__device__ __forceinline__ void cp_async16(void* sdst, const void* gsrc) {
    unsigned s = (unsigned)__cvta_generic_to_shared(sdst);
    asm volatile("cp.async.cg.shared.global [%0], [%1], 16;" :: "r"(s), "l"(gsrc));
}
__device__ __forceinline__ void cp_commit() { asm volatile("cp.async.commit_group;"); }
__device__ __forceinline__ void cp_wait0()  { asm volatile("cp.async.wait_group 0;" ::: "memory"); }

// ---------------------------------------------------------------------------
// Pass 1: S[d][e] = sum_s V[s][d] * K[s][e] per (bh, chunk); S written fp16.
// Pure fp16 operands, fp32 accumulate. 16 mma per warp. 18.4KB smem ->
// entire 1024-CTA grid resident in one wave.
// ---------------------------------------------------------------------------
#define SMEM1_BYTES (2 * HB_ * 2)   // 18432

__global__ void __launch_bounds__(128) chunk_sum_kernel(const float* __restrict__ k,
                                                        const float* __restrict__ v) {
    extern __shared__ __align__(16) char smraw1[];
    __half* K16 = (__half*)smraw1;
    __half* V16 = K16 + HB_;
    float*  Sraw = (float*)smraw1;    // [64][68] fp32 pack staging, aliases after mma

    int blk = blockIdx.x;             // [0, 1024)
    int bh  = blk >> 6;
    int c   = blk & (NC_ - 1);
    int b   = bh >> 3, h = bh & 7;
    int tid = threadIdx.x;

    const float* kbase = k + (((size_t)b * T_ + (size_t)c * C_) * H_ + h) * D_;
    const float* vbase = v + (((size_t)b * T_ + (size_t)c * C_) * H_ + h) * D_;

    #pragma unroll
    for (int f = tid; f < C_ * D_ / 4; f += 128) {
        int s = f >> 4;
        int cc = (f & 15) * 4;
        quant_store4(K16, s * SB_ + cc,
                     *(const float4*)(kbase + (size_t)s * ROWSTRIDE + cc));
        quant_store4(V16, s * SB_ + cc,
                     *(const float4*)(vbase + (size_t)s * ROWSTRIDE + cc));
    }
    __syncthreads();

    int wid = tid >> 5;
    int d0 = wid * 16;

    FragAcc acc[4];
    #pragma unroll
    for (int j = 0; j < 4; j++) wmma::fill_fragment(acc[j], 0.f);

    #pragma unroll
    for (int kk = 0; kk < 4; kk++) {
        int s0 = kk * 16;
        FragAC av;
        wmma::load_matrix_sync(av, &V16[s0 * SB_ + d0], SB_);    // A(d,s)=V[s][d]
        #pragma unroll
        for (int j = 0; j < 4; j++) {
            FragBR bq;
            wmma::load_matrix_sync(bq, &K16[s0 * SB_ + j * 16], SB_); // B(s,e)=K[s][e]
            wmma::mma_sync(acc[j], av, bq, acc[j]);
        }
    }
    __syncthreads();   // all LDSM reads done before Sraw overwrites

    #pragma unroll
    for (int j = 0; j < 4; j++)
        wmma::store_matrix_sync(&Sraw[d0 * SRW_ + j * 16], acc[j], SRW_, wmma::mem_row_major);
    __syncthreads();

    __half* Sout = g_Sh + (size_t)blk * D_ * D_;
    #pragma unroll
    for (int f = tid; f < D_ * D_ / 4; f += 128) {
        int r = f >> 4;
        int cc = (f & 15) * 4;
        quant_store4(Sout, f * 4, *(const float4*)&Sraw[r * SRW_ + cc]);
    }
}

// ---------------------------------------------------------------------------
// Pass 2: exclusive prefix over the chunk axis; fp16 in (S), fp16 out (M).
// ---------------------------------------------------------------------------
__global__ void __launch_bounds__(256) prefix_kernel() {
    int gidx = blockIdx.x * 256 + threadIdx.x;   // [0, BH_*2048)
    int bh   = gidx >> 11;
    int pidx = gidx & 2047;
    const __half2* src = (const __half2*)g_Sh + (size_t)bh * NC_ * 2048 + pidx;
    __half2*       dst = (__half2*)g_M  + (size_t)bh * NC_ * 2048 + pidx;

    __half2 vals[NC_];
    #pragma unroll
    for (int c = 0; c < NC_; c++) vals[c] = src[(size_t)c * 2048];
    float rx = 0.f, ry = 0.f;
    #pragma unroll
    for (int c = 0; c < NC_; c++) {
        float2 t = __half22float2(vals[c]);
        dst[(size_t)c * 2048] = __floats2half2_rn(rx, ry);
        rx += t.x; ry += t.y;
    }
}

// ---------------------------------------------------------------------------
// Pass 3: Y = tril(Q K^T) V + Q M_prev^T per (bh, chunk).
// Pure fp16 operands, fp32 accumulate: 48 mma per warp total.
// Score region (18KB fp32) reused as Shi (first 9KB) + M16 (second 9KB).
// smem 45KB -> 5 CTAs/SM.
// ---------------------------------------------------------------------------
#define SMEM3_BYTES (3 * HB_ * 2 + HB_ * 4)   // 27648 + 18432 = 46080

__global__ void __launch_bounds__(128) output_kernel(const float* __restrict__ q,
                                                     const float* __restrict__ k,
                                                     const float* __restrict__ v,
                                                     float* __restrict__ y) {
    extern __shared__ __align__(16) char smraw[];
    __half* Q16 = (__half*)smraw;
    __half* K16 = Q16 + HB_;
    __half* V16 = K16 + HB_;
    float*  Sraw = (float*)(V16 + HB_);   // fp32 [64][72] (18432B region)
    __half* Shi  = (__half*)Sraw;         // first 9216B after mask
    __half* M16  = (__half*)Sraw + HB_;   // second 9216B (disjoint from Shi)

    int blk = blockIdx.x;             // [0, 1024)
    int bh  = blk >> 6;
    int c   = blk & (NC_ - 1);
    int b   = bh >> 3, h = bh & 7;
    int tid = threadIdx.x;

    const float* qbase = q + (((size_t)b * T_ + (size_t)c * C_) * H_ + h) * D_;
    const float* kbase = k + (((size_t)b * T_ + (size_t)c * C_) * H_ + h) * D_;
    const float* vbase = v + (((size_t)b * T_ + (size_t)c * C_) * H_ + h) * D_;
    const __half* Mg = g_M + (size_t)blk * D_ * D_;

    #pragma unroll
    for (int f = tid; f < C_ * D_ / 4; f += 128) {
        int s = f >> 4;
        int cc = (f & 15) * 4;
        quant_store4(Q16, s * SB_ + cc,
                     *(const float4*)(qbase + (size_t)s * ROWSTRIDE + cc));
        quant_store4(K16, s * SB_ + cc,
                     *(const float4*)(kbase + (size_t)s * ROWSTRIDE + cc));
        quant_store4(V16, s * SB_ + cc,
                     *(const float4*)(vbase + (size_t)s * ROWSTRIDE + cc));
    }
    __syncthreads();

    int wid = tid >> 5;
    int t0 = wid * 16;

    // ---- Phase 1: scores S[t][s] = sum_e Q[t][e] K[s][e]   (16 mma)
    FragAcc acc[4];
    #pragma unroll
    for (int j = 0; j < 4; j++) wmma::fill_fragment(acc[j], 0.f);
    #pragma unroll
    for (int kk = 0; kk < 4; kk++) {
        int e0 = kk * 16;
        FragAR aq;
        wmma::load_matrix_sync(aq, &Q16[t0 * SB_ + e0], SB_);
        #pragma unroll
        for (int j = 0; j < 4; j++) {
            FragBC bk;
            wmma::load_matrix_sync(bk, &K16[(j * 16) * SB_ + e0], SB_); // B(e,s)=K[s][e]
            wmma::mma_sync(acc[j], aq, bk, acc[j]);
        }
    }
    #pragma unroll
    for (int j = 0; j < 4; j++)
        wmma::store_matrix_sync(&Sraw[t0 * SB_ + j * 16], acc[j], SB_, wmma::mem_row_major);
    __syncthreads();

    // ---- Causal mask (s <= t): fp32 reads into registers, then fp16 writes
    float r[32];
    #pragma unroll
    for (int i = 0; i < 32; i++) {
        int f = tid + i * 128;
        int t = f >> 6, s = f & 63;
        r[i] = Sraw[t * SB_ + s];
    }
    __syncthreads();   // all fp32 reads done before the region is rewritten

    // Fire the M prefetch into the second half of the freed region...
    #pragma unroll
    for (int f = tid; f < D_ * D_ / 8; f += 128) {
        int d = f >> 3;
        int c8 = (f & 7) * 8;
        cp_async16(&M16[d * SB_ + c8], Mg + d * D_ + c8);
    }
    cp_commit();

    // ...while writing the masked fp16 A into the first half.
    #pragma unroll
    for (int i = 0; i < 32; i++) {
        int f = tid + i * 128;
        int t = f >> 6, s = f & 63;
        float x = (s <= t) ? r[i] : 0.f;
        Shi[t * SB_ + s] = __float2half_rn(x);
    }
    cp_wait0();
    __syncthreads();

    // ---- Phase 2: Y = Q M^T + A V   (32 mma)
    #pragma unroll
    for (int j = 0; j < 4; j++) wmma::fill_fragment(acc[j], 0.f);
    #pragma unroll
    for (int kk = 0; kk < 4; kk++) {
        int e0 = kk * 16;
        FragAR aq;
        wmma::load_matrix_sync(aq, &Q16[t0 * SB_ + e0], SB_);
        #pragma unroll
        for (int j = 0; j < 4; j++) {
            FragBC bm;
            wmma::load_matrix_sync(bm, &M16[(j * 16) * SB_ + e0], SB_); // B(e,d)=M[d][e]
            wmma::mma_sync(acc[j], aq, bm, acc[j]);
        }
    }
    #pragma unroll
    for (int kk = 0; kk < 4; kk++) {
        int s0 = kk * 16;
        FragAR aa;
        wmma::load_matrix_sync(aa, &Shi[t0 * SB_ + s0], SB_);
        #pragma unroll
        for (int j = 0; j < 4; j++) {
            FragBR bv;
            wmma::load_matrix_sync(bv, &V16[s0 * SB_ + j * 16], SB_);  // B(s,d)=V[s][d]
            wmma::mma_sync(acc[j], aa, bv, acc[j]);
        }
    }

    float* ybase = y + (((size_t)b * T_ + (size_t)c * C_) * H_ + h) * D_;
    #pragma unroll
    for (int j = 0; j < 4; j++)
        wmma::store_matrix_sync(ybase + (size_t)t0 * ROWSTRIDE + j * 16, acc[j],
                                ROWSTRIDE, wmma::mem_row_major);
}

// ---------------------------------------------------------------------------
extern "C" void kernel_launch(void* const* d_in, const int* in_sizes, int n_in,
                              void* d_out, int out_size) {
    (void)in_sizes; (void)n_in; (void)out_size;
    const float* q = (const float*)d_in[0];
    const float* k = (const float*)d_in[1];
    const float* v = (const float*)d_in[2];
    float* y = (float*)d_out;

    cudaFuncSetAttribute(output_kernel, cudaFuncAttributeMaxDynamicSharedMemorySize,
                         SMEM3_BYTES);

    chunk_sum_kernel<<<BH_ * NC_, 128, SMEM1_BYTES>>>(k, v);
    prefix_kernel<<<(BH_ * 2048) / 256, 256>>>();
    output_kernel<<<BH_ * NC_, 128, SMEM3_BYTES>>>(q, k, v, y);
}